// round 17
// baseline (speedup 1.0000x reference)
#include <cuda_runtime.h>
#include <cuda_fp16.h>
#include <math.h>
#include <stdint.h>

#define BB 2
#define LL 4096
#define DDIM 2048
#define D3 (3*DDIM)
#define HH 8
#define DH 256
#define BT 64
#define NC 64          // LL / BT
#define BLD (BB*LL*DDIM)
#define DD2 (DDIM*DDIM)
#define QS 260         // padded fp32 tile stride (solve)
#define SCS 36         // S / Un / P row stride (floats)
#define QHS 264        // fp16 staged tile stride (halfs): 256 data + 8 pad = 528 B
#define THS 72         // fp16 T stride (halfs)

// -------------------- scratch (device globals; no allocation) --------------------
__device__ __align__(128) __half g_preh[(size_t)BB*LL*D3];  // fused QKV pre-activations fp16
__device__ float g_qt[BLD];       // fp32 q (attn-in-solve)
__device__ float g_kt[BLD];       // fp32 k (solve)
__device__ float g_vt[BLD];
__device__ float g_ut[BLD];
__device__ float g_beta[BB*HH*LL];
__device__ float g_og[BLD];
__device__ __align__(128) __half g_qh[BLD];     // fp16 q (scan)
__device__ __align__(128) __half g_khT[BLD];    // fp16 k transposed per chunk
__device__ __align__(128) __half g_ws[BLD];     // fp16 W (scan)
__device__ __align__(128) __half g_atth[(size_t)BB*HH*NC*BT*BT];
__device__ __align__(128) __half g_ah[BLD];     // activation fp16 (GEMM A)
__device__ __align__(128) __half g_wh[4*DD2];   // weights fp16 (Wq,Wk,Wv,Wo)

// -------------------- helpers --------------------
__device__ __forceinline__ unsigned long long pack2dup(float x) {
  unsigned long long r;
  asm("mov.b64 %0, {%1,%1};" : "=l"(r) : "f"(x));
  return r;
}
__device__ __forceinline__ void unpack2(unsigned long long v, float& x, float& y) {
  asm("mov.b64 {%0,%1}, %2;" : "=f"(x), "=f"(y) : "l"(v));
}
__device__ __forceinline__ void fma2(unsigned long long& d,
                                     unsigned long long a, unsigned long long b) {
  asm("fma.rn.f32x2 %0, %1, %2, %0;" : "+l"(d) : "l"(a), "l"(b));
}
__device__ __forceinline__ uint32_t h2(float x, float y) {
  __half2 h = __floats2half2_rn(x, y);
  return *(uint32_t*)&h;
}

// ==================== converts ====================
__global__ __launch_bounds__(256) void cvt_kernel(
    const float* __restrict__ x, __half* __restrict__ h, int n4)
{
  int i = blockIdx.x * blockDim.x + threadIdx.x;
  if (i >= n4) return;
  float4 v = *(const float4*)(x + (size_t)i * 4);
  __half2* hp = (__half2*)(h + (size_t)i * 4);
  hp[0] = __floats2half2_rn(v.x, v.y);
  hp[1] = __floats2half2_rn(v.z, v.w);
}

// 4 weight matrices in one launch; which = blk >> 12 (DD2/4/256 = 4096 blocks each)
__global__ __launch_bounds__(256) void cvt4_kernel(
    const float* __restrict__ w0, const float* __restrict__ w1,
    const float* __restrict__ w2, const float* __restrict__ w3,
    __half* __restrict__ h)
{
  int blk = blockIdx.x;
  int which = blk >> 12;
  int i = (blk & 4095) * 256 + threadIdx.x;
  const float* src = which == 0 ? w0 : which == 1 ? w1 : which == 2 ? w2 : w3;
  float4 v = *(const float4*)(src + (size_t)i * 4);
  __half* dst = h + (size_t)which * DD2;
  __half2* hp = (__half2*)(dst + (size_t)i * 4);
  hp[0] = __floats2half2_rn(v.x, v.y);
  hp[1] = __floats2half2_rn(v.z, v.w);
}

// ==================== fp16 HMMA GEMM, BK=32, 4-stage cp.async ====================
#define GSTRIDE 40
#define GTILE (128*GSTRIDE)
#define ABYTES (GTILE*2)
#define STAGEB (2*ABYTES)
#define NSTAGE 4
#define GEMM_SMEM (NSTAGE*STAGEB)

__device__ __forceinline__ void cpa16(uint32_t dst, const void* src) {
  asm volatile("cp.async.ca.shared.global [%0], [%1], 16;" :: "r"(dst), "l"(src));
}
#define CP_COMMIT() asm volatile("cp.async.commit_group;" ::: "memory")
#define CP_WAIT(n)  asm volatile("cp.async.wait_group %0;" :: "n"(n) : "memory")

__device__ __forceinline__ void ldsm4(uint32_t* r, uint32_t addr) {
  asm volatile("ldmatrix.sync.aligned.m8n8.x4.shared.b16 {%0,%1,%2,%3}, [%4];"
    : "=r"(r[0]), "=r"(r[1]), "=r"(r[2]), "=r"(r[3]) : "r"(addr));
}
__device__ __forceinline__ void mma16816(float* d, const uint32_t* a, uint32_t b0, uint32_t b1) {
  asm volatile("mma.sync.aligned.m16n8k16.row.col.f32.f16.f16.f32 "
    "{%0,%1,%2,%3}, {%4,%5,%6,%7}, {%8,%9}, {%0,%1,%2,%3};"
    : "+f"(d[0]), "+f"(d[1]), "+f"(d[2]), "+f"(d[3])
    : "r"(a[0]), "r"(a[1]), "r"(a[2]), "r"(a[3]), "r"(b0), "r"(b1));
}

__device__ __forceinline__ void load_stage_async(
    const __half* __restrict__ A, const __half* __restrict__ B,
    int bm, int bn, int K, int k0, uint32_t sb, int tid)
{
  const __half* srcs[2] = {A, B};
  const int rb[2] = {bm, bn};
#pragma unroll
  for (int a = 0; a < 2; a++) {
#pragma unroll
    for (int i = 0; i < 2; i++) {
      int idx = tid + i * 256;
      int r = idx >> 2, ch = idx & 3;
      const __half* g = srcs[a] + (size_t)(rb[a] + r) * K + k0 + ch * 8;
      uint32_t dst = sb + a * ABYTES + (uint32_t)(r * 80 + ch * 16);
      cpa16(dst, g);
    }
  }
}

__global__ __launch_bounds__(256, 2) void gemm_h_kernel(
    const __half* __restrict__ A, const __half* __restrict__ B,
    float* __restrict__ C, __half* __restrict__ Ch,
    int M, int N, int K, int out_half)
{
  extern __shared__ char sm[];
  const int tid = threadIdx.x, lane = tid & 31, wid = tid >> 5;
  const int warp_m = wid >> 2, warp_n = wid & 3;
  const int bm = blockIdx.y * 128, bn = blockIdx.x * 128;
  const uint32_t sbase = (uint32_t)__cvta_generic_to_shared(sm);

  float acc[4][4][4];
#pragma unroll
  for (int i = 0; i < 4; i++)
#pragma unroll
    for (int j = 0; j < 4; j++)
#pragma unroll
      for (int e = 0; e < 4; e++) acc[i][j][e] = 0.f;

  const int NT = K / 32;
#pragma unroll
  for (int p = 0; p < NSTAGE - 1; p++) {
    load_stage_async(A, B, bm, bn, K, p * 32, sbase + p * STAGEB, tid);
    CP_COMMIT();
  }

  const int arow  = warp_m * 64 + (lane & 15);
  const int acol0 = (lane >> 4) * 8;
  const int brow  = warp_n * 32 + (lane >> 4) * 8 + (lane & 7);
  const int bcol0 = ((lane >> 3) & 1) * 8;

  for (int kt = 0; kt < NT; kt++) {
    CP_WAIT(NSTAGE - 2);
    __syncthreads();
    {
      int knext = kt + NSTAGE - 1;
      int kc = knext < NT ? knext : NT - 1;
      load_stage_async(A, B, bm, bn, K, kc * 32, sbase + (knext & (NSTAGE - 1)) * STAGEB, tid);
      CP_COMMIT();
    }
    const uint32_t stb = sbase + (kt & (NSTAGE - 1)) * STAGEB;
    const uint32_t aoff = stb;
    const uint32_t boff = stb + ABYTES;
#pragma unroll
    for (int kk = 0; kk < 32; kk += 16) {
      uint32_t af[4][4], bf[2][4];
#pragma unroll
      for (int mt = 0; mt < 4; mt++) {
        uint32_t ab = (uint32_t)(((arow + mt * 16) * GSTRIDE + kk + acol0) * 2);
        ldsm4(af[mt], aoff + ab);
      }
#pragma unroll
      for (int p = 0; p < 2; p++) {
        uint32_t bb = (uint32_t)(((brow + p * 16) * GSTRIDE + kk + bcol0) * 2);
        ldsm4(bf[p], boff + bb);
      }
#pragma unroll
      for (int mt = 0; mt < 4; mt++)
#pragma unroll
        for (int nt = 0; nt < 4; nt++) {
          const uint32_t* bp = bf[nt >> 1];
          int bi = (nt & 1) * 2;
          mma16816(acc[mt][nt], af[mt], bp[bi], bp[bi + 1]);
        }
    }
  }
  __syncthreads();
  const int row0 = bm + warp_m * 64 + (lane >> 2);
  const int col0 = bn + warp_n * 32 + (lane & 3) * 2;
  if (out_half) {
#pragma unroll
    for (int mt = 0; mt < 4; mt++)
#pragma unroll
      for (int nt = 0; nt < 4; nt++) {
        int r = row0 + mt * 16;
        int c = col0 + nt * 8;
        *(__half2*)(Ch + (size_t)r * N + c) =
            __floats2half2_rn(acc[mt][nt][0], acc[mt][nt][1]);
        *(__half2*)(Ch + (size_t)(r + 8) * N + c) =
            __floats2half2_rn(acc[mt][nt][2], acc[mt][nt][3]);
      }
  } else {
#pragma unroll
    for (int mt = 0; mt < 4; mt++)
#pragma unroll
      for (int nt = 0; nt < 4; nt++) {
        int r = row0 + mt * 16;
        int c = col0 + nt * 8;
        *(float2*)(C + (size_t)r * N + c)       = make_float2(acc[mt][nt][0], acc[mt][nt][1]);
        *(float2*)(C + (size_t)(r + 8) * N + c) = make_float2(acc[mt][nt][2], acc[mt][nt][3]);
      }
  }
}

// -------------------- beta = sigmoid(hs @ Wb^T), [B,H,L] --------------------
__global__ __launch_bounds__(256) void beta_kernel(
    const float* __restrict__ hs, const float* __restrict__ Wb, float* __restrict__ beta)
{
  int bl = blockIdx.x;
  int b = bl / LL, l = bl % LL;
  int w = threadIdx.x >> 5, lane = threadIdx.x & 31;
  const float* x = hs + (size_t)bl * DDIM;
  const float* wb = Wb + (size_t)w * DDIM;
  float s = 0.f;
  for (int d = lane; d < DDIM; d += 32) s += x[d] * wb[d];
#pragma unroll
  for (int o = 16; o; o >>= 1) s += __shfl_xor_sync(0xffffffffu, s, o);
  if (lane == 0)
    beta[((size_t)b * HH + w) * LL + l] = 1.f / (1.f + expf(-s));
}

// -------- fused conv + SiLU (+l2norm), fp16 input; all 3 modes in one launch --------
__global__ __launch_bounds__(256) void conv_kernel(
    const __half* __restrict__ pre, const float* __restrict__ cwq,
    const float* __restrict__ cwk, const float* __restrict__ cwv,
    float* __restrict__ qt, float* __restrict__ kt, float* __restrict__ vt,
    __half* __restrict__ qh, __half* __restrict__ khT)
{
  int blk0 = blockIdx.x;
  int mode = blk0 >> 13;                    // 8192 blocks per mode
  int blk = blk0 & 8191;
  const float* cw = mode == 0 ? cwq : mode == 1 ? cwk : cwv;
  float* out = mode == 0 ? qt : mode == 1 ? kt : vt;
  int lt = blk & (LL / 8 - 1);
  int bh = blk >> 9;
  int h = bh % HH, b = bh / HH;
  int w = threadIdx.x >> 5, lane = threadIdx.x & 31;
  int l = lt * 8 + w;
  const __half* base = pre + (size_t)(b * LL) * D3 + mode * DDIM + h * DH;
  float y[2][4];
  float ss = 0.f;
#pragma unroll
  for (int j = 0; j < 2; j++) {
    int dd = lane * 4 + j * 128;
    int c = h * DH + dd;
    float xs[4][4];
#pragma unroll
    for (int tap = 0; tap < 4; tap++) {
      if (l >= tap) {
        uint2 raw = *(const uint2*)(base + (size_t)(l - tap) * D3 + dd);
        float2 f01 = __half22float2(*(__half2*)&raw.x);
        float2 f23 = __half22float2(*(__half2*)&raw.y);
        xs[0][tap] = f01.x; xs[1][tap] = f01.y; xs[2][tap] = f23.x; xs[3][tap] = f23.y;
      } else {
        xs[0][tap] = 0.f; xs[1][tap] = 0.f; xs[2][tap] = 0.f; xs[3][tap] = 0.f;
      }
    }
#pragma unroll
    for (int ci = 0; ci < 4; ci++) {
      float4 cv = *(const float4*)(cw + (size_t)(c + ci) * 4);
      float acc = xs[ci][0] * cv.w + xs[ci][1] * cv.z + xs[ci][2] * cv.y + xs[ci][3] * cv.x;
      float yy = acc / (1.f + expf(-acc));
      y[j][ci] = yy;
      ss += yy * yy;
    }
  }
  float scale = 1.f;
  if (mode < 2) {
#pragma unroll
    for (int o = 16; o; o >>= 1) ss += __shfl_xor_sync(0xffffffffu, ss, o);
    scale = rsqrtf(ss + 1e-6f);
    if (mode == 0) scale *= 0.0625f;
  }
  size_t ob = (((size_t)b * HH + h) * LL + l) * DH;
  float* op = out + ob;
  int cch = l >> 6, tloc = l & 63;
  __half* tp = khT + ((size_t)(b * HH + h) * NC + cch) * (DH * BT);
#pragma unroll
  for (int j = 0; j < 2; j++) {
    int dd = lane * 4 + j * 128;
    float4 yv = make_float4(y[j][0] * scale, y[j][1] * scale,
                            y[j][2] * scale, y[j][3] * scale);
    *(float4*)(op + dd) = yv;
    if (mode == 0) {
      uint2 hv;
      hv.x = h2(yv.x, yv.y);
      hv.y = h2(yv.z, yv.w);
      *(uint2*)(qh + ob + dd) = hv;
    } else if (mode == 1) {
      tp[(dd + 0) * BT + tloc] = __float2half_rn(yv.x);
      tp[(dd + 1) * BT + tloc] = __float2half_rn(yv.y);
      tp[(dd + 2) * BT + tloc] = __float2half_rn(yv.z);
      tp[(dd + 3) * BT + tloc] = __float2half_rn(yv.w);
    }
  }
}

// -------- solve + fused attn: warps 0-7 do substitution, warps 8-15 do attn --------
#define SOLVE_SMEM ((3*64*QS + 64*64 + 64) * 4)
__global__ __launch_bounds__(512) void solve_kernel(
    const float* __restrict__ kt, const float* __restrict__ vt,
    const float* __restrict__ qt, const float* __restrict__ beta,
    __half* __restrict__ Wh_g, float* __restrict__ Ut, __half* __restrict__ atth)
{
  extern __shared__ float sh[];
  float* sk = sh;
  float* sw = sk + 64 * QS;
  float* su = sw + 64 * QS;
  float* sM = su + 64 * QS;
  float* sbeta = sM + 64 * 64;
  int blk = blockIdx.x;
  int c = blk % NC, bh = blk / NC;
  size_t base = ((size_t)bh * LL + (size_t)c * BT) * DH;
  int tid = threadIdx.x;

  if (tid < 64) sbeta[tid] = beta[(size_t)bh * LL + c * BT + tid];
  __syncthreads();
  for (int i = tid; i < 4096; i += 512) {
    int t = i >> 6, dd = (i & 63) * 4;
    float bt = sbeta[t];
    float4 kv = *(const float4*)(kt + base + (size_t)t * DH + dd);
    float4 vv = *(const float4*)(vt + base + (size_t)t * DH + dd);
    *(float4*)&sk[t * QS + dd] = kv;
    *(float4*)&sw[t * QS + dd] = make_float4(kv.x * bt, kv.y * bt, kv.z * bt, kv.w * bt);
    *(float4*)&su[t * QS + dd] = make_float4(vv.x * bt, vv.y * bt, vv.z * bt, vv.w * bt);
  }
  __syncthreads();
  // M = strict_lower(kb @ k^T)
  {
    int tp = tid >> 4, sb = tid & 15;
    int t0 = tp * 2, t1 = t0 + 1;
    unsigned long long acc[2][4];
#pragma unroll
    for (int ti = 0; ti < 2; ti++)
#pragma unroll
      for (int si = 0; si < 4; si++) acc[ti][si] = 0;
    if (sb < t1) {
      const float* q0 = &sw[t0 * QS];
      const float* q1 = &sw[t1 * QS];
#pragma unroll 2
      for (int d = 0; d < DH; d += 4) {
        ulonglong2 a0 = *(const ulonglong2*)(q0 + d);
        ulonglong2 a1 = *(const ulonglong2*)(q1 + d);
#pragma unroll
        for (int si = 0; si < 4; si++) {
          ulonglong2 kv = *(const ulonglong2*)(&sk[(sb + si * 16) * QS + d]);
          fma2(acc[0][si], a0.x, kv.x); fma2(acc[0][si], a0.y, kv.y);
          fma2(acc[1][si], a1.x, kv.x); fma2(acc[1][si], a1.y, kv.y);
        }
      }
    }
#pragma unroll
    for (int ti = 0; ti < 2; ti++)
#pragma unroll
      for (int si = 0; si < 4; si++) {
        int t = t0 + ti, s = sb + si * 16;
        float x0, x1;
        unpack2(acc[ti][si], x0, x1);
        sM[t * 64 + s] = (s < t) ? (x0 + x1) : 0.f;
      }
  }
  __syncthreads();
  if (tid < 128) {
    // forward substitution for W (2 cols per thread)
    int d = tid * 2;
    for (int t = 1; t < BT; t++) {
      unsigned long long acc = 0;
      const float* Mr = &sM[t * 64];
      for (int s = 0; s < t; s++)
        fma2(acc, pack2dup(Mr[s]), *(const unsigned long long*)&sw[s * QS + d]);
      float a0, a1;
      unpack2(acc, a0, a1);
      sw[t * QS + d]     -= a0;
      sw[t * QS + d + 1] -= a1;
    }
  } else if (tid < 256) {
    // forward substitution for U
    int d = (tid - 128) * 2;
    for (int t = 1; t < BT; t++) {
      unsigned long long acc = 0;
      const float* Mr = &sM[t * 64];
      for (int s = 0; s < t; s++)
        fma2(acc, pack2dup(Mr[s]), *(const unsigned long long*)&su[s * QS + d]);
      float a0, a1;
      unpack2(acc, a0, a1);
      su[t * QS + d]     -= a0;
      su[t * QS + d + 1] -= a1;
    }
  } else {
    // warps 8-15: attn = tril(q k^T) -> fp16 (q from global, k from smem sk)
    int tid2 = tid - 256;
    __half* ap = atth + (size_t)blk * (BT * BT);
#pragma unroll
    for (int i = 0; i < 16; i++) {
      int e = tid2 + 256 * i;
      int t = e >> 6, s = e & 63;
      __half r = __float2half_rn(0.f);
      if (s <= t) {
        unsigned long long a0 = 0, a1 = 0;
        const float* qp = qt + base + (size_t)t * DH;
        const float* kp = &sk[s * QS];
#pragma unroll 4
        for (int d = 0; d < DH; d += 4) {
          ulonglong2 qv = *(const ulonglong2*)(qp + d);
          ulonglong2 kv = *(const ulonglong2*)(kp + d);
          fma2(a0, qv.x, kv.x);
          fma2(a1, qv.y, kv.y);
        }
        float x0, x1, x2, x3;
        unpack2(a0, x0, x1);
        unpack2(a1, x2, x3);
        r = __float2half_rn((x0 + x1) + (x2 + x3));
      }
      ap[e] = r;
    }
  }
  __syncthreads();
  for (int i = tid; i < 4096; i += 512) {
    int t = i >> 6, dd = (i & 63) * 4;
    float4 wv = *(float4*)&sw[t * QS + dd];
    uint2 hv;
    hv.x = h2(wv.x, wv.y);
    hv.y = h2(wv.z, wv.w);
    *(uint2*)(Wh_g + base + (size_t)t * DH + dd) = hv;
    *(float4*)(Ut + base + (size_t)t * DH + dd) = *(float4*)&su[t * QS + dd];
  }
}

// -------------------- scan: fused A+B (full-K warps), 2 syncs/chunk --------------------
#define STG_Q 33792                              // 64 rows * 528 B
#define STG_T 9216                               // 64 rows * 144 B
#define STG_BYTES (2*STG_Q + STG_T)              // 76800
#define SCAN_SMEM (36864 + 9216 + 9216 + 2*STG_BYTES)   // 208896

__device__ __forceinline__ void scan_stage_async(
    const __half* __restrict__ qh, const __half* __restrict__ wh,
    const __half* __restrict__ th,
    size_t base, size_t abase, uint32_t sb, int tid)
{
#pragma unroll
  for (int it = 0; it < 8; it++) {
    int i = tid + it * 512;
    int a = i >> 11;
    int r = (i >> 5) & 63;
    int d8 = i & 31;
    const __half* src = (a ? wh : qh) + base + (size_t)r * DH + d8 * 8;
    cpa16(sb + a * STG_Q + (uint32_t)(r * 528 + d8 * 16), src);
  }
  {
    int tt = tid >> 3, cc = tid & 7;
    cpa16(sb + 2 * STG_Q + (uint32_t)(tt * 144 + cc * 16), th + abase + tt * 64 + cc * 8);
  }
}

__global__ __launch_bounds__(512) void scan_kernel(
    const __half* __restrict__ qh, const __half* __restrict__ khT,
    const __half* __restrict__ wh, const float* __restrict__ ut,
    const __half* __restrict__ atth, float* __restrict__ og)
{
  extern __shared__ char smc[];
  float* S  = (float*)smc;
  float* Un = (float*)(smc + 36864);
  float* P  = (float*)(smc + 46080);
  char*  stg = smc + 55296;
  const uint32_t stg_s0 = (uint32_t)__cvta_generic_to_shared(stg);

  int blk = blockIdx.x;
  int vb = blk & 7;
  int bh = blk >> 3;
  int b = bh / HH, h = bh % HH;
  int tid = threadIdx.x;
  int lane = tid & 31, wrp = tid >> 5;
  int fr = lane >> 2;
  int fc = (lane & 3) * 2;
  int dw = wrp * 16;
  int which = wrp >> 3;
  int sub = wrp & 7;
  int ttile = sub >> 1;
  int nh = sub & 1;
  int tb = ttile * 16;
  int cmt = wrp >> 2;
  int cnt = wrp & 3;
  int ctb = cmt * 16, cnb = cnt * 8;

  for (int i = tid; i < 256 * SCS; i += 512) S[i] = 0.f;

  {
    size_t base0 = ((size_t)bh * LL) * DH;
    size_t abase0 = (size_t)bh * NC * 4096;
    scan_stage_async(qh, wh, atth, base0, abase0, stg_s0, tid);
    CP_COMMIT();
  }
  CP_WAIT(0);
  __syncthreads();

  for (int c = 0; c < NC; c++) {
    size_t base = ((size_t)bh * LL + (size_t)c * BT) * DH;
    char* sb_c = stg + (c & 1) * STG_BYTES;
    const __half* Qh = (const __half*)sb_c;
    const __half* Wh = (const __half*)(sb_c + STG_Q);
    const __half* Th = (const __half*)(sb_c + 2 * STG_Q);

    if (c + 1 < NC) {
      size_t basen = ((size_t)bh * LL + (size_t)(c + 1) * BT) * DH;
      size_t abasen = ((size_t)bh * NC + (c + 1)) * 4096;
      scan_stage_async(qh, wh, atth, basen, abasen,
                       stg_s0 + ((c + 1) & 1) * STG_BYTES, tid);
      CP_COMMIT();
    }

    uint32_t ka[4][4];
    {
      const __half* ktile = khT + ((size_t)bh * NC + c) * (DH * BT);
      const __half* kr0 = ktile + (dw + fr) * BT;
      const __half* kr1 = ktile + (dw + fr + 8) * BT;
#pragma unroll
      for (int s = 0; s < 4; s++) {
        int kk = s * 16;
        ka[s][0] = *(const uint32_t*)(kr0 + kk + fc);
        ka[s][1] = *(const uint32_t*)(kr1 + kk + fc);
        ka[s][2] = *(const uint32_t*)(kr0 + kk + fc + 8);
        ka[s][3] = *(const uint32_t*)(kr1 + kk + fc + 8);
      }
    }

    // ---- Phase A+B fused ----
    {
      float acc[2][4];
#pragma unroll
      for (int vt = 0; vt < 2; vt++)
#pragma unroll
        for (int e = 0; e < 4; e++) acc[vt][e] = 0.f;
      const __half* Ab = which ? Wh : Qh;
      const __half* ar0 = Ab + (tb + fr) * QHS;
      const __half* ar1 = Ab + (tb + fr + 8) * QHS;
#pragma unroll
      for (int kk = 0; kk < DH; kk += 16) {
        uint32_t a[4];
        a[0] = *(const uint32_t*)(ar0 + kk + fc);
        a[1] = *(const uint32_t*)(ar1 + kk + fc);
        a[2] = *(const uint32_t*)(ar0 + kk + fc + 8);
        a[3] = *(const uint32_t*)(ar1 + kk + fc + 8);
        const float* s0 = &S[(kk + fc) * SCS];
        const float* s1 = &S[(kk + fc + 1) * SCS];
        const float* s8 = &S[(kk + fc + 8) * SCS];
        const float* s9 = &S[(kk + fc + 9) * SCS];
#pragma unroll
        for (int vt = 0; vt < 2; vt++) {
          int vn = (nh * 2 + vt) * 8 + fr;
          uint32_t b0 = h2(s0[vn], s1[vn]);
          uint32_t b1 = h2(s8[vn], s9[vn]);
          mma16816(acc[vt], a, b0, b1);
        }
      }
      if (which == 0) {
#pragma unroll
        for (int vt = 0; vt < 2; vt++) {
          int vc = (nh * 2 + vt) * 8 + fc;
          *(float2*)&P[(tb + fr) * SCS + vc]       = make_float2(acc[vt][0], acc[vt][1]);
          *(float2*)&P[(tb + fr + 8) * SCS + vc]   = make_float2(acc[vt][2], acc[vt][3]);
        }
      } else {
        size_t ub0 = base + (size_t)(tb + fr) * DH + vb * 32;
        size_t ub1 = base + (size_t)(tb + fr + 8) * DH + vb * 32;
#pragma unroll
        for (int vt = 0; vt < 2; vt++) {
          int vc = (nh * 2 + vt) * 8 + fc;
          float2 u0 = *(const float2*)(ut + ub0 + vc);
          float2 u1 = *(const float2*)(ut + ub1 + vc);
          *(float2*)&Un[(tb + fr) * SCS + vc] =
              make_float2(u0.x - acc[vt][0], u0.y - acc[vt][1]);
          *(float2*)&Un[(tb + fr + 8) * SCS + vc] =
              make_float2(u1.x - acc[vt][2], u1.y - acc[vt][3]);
        }
      }
    }
    __syncthreads();

    // ---- Phase C ----
    {
      float cacc[4] = {0.f, 0.f, 0.f, 0.f};
#pragma unroll
      for (int kk = 0; kk < BT; kk += 16) {
        const __half* t0p = Th + (ctb + fr) * THS + kk;
        const __half* t1p = Th + (ctb + fr + 8) * THS + kk;
        uint32_t a[4];
        a[0] = *(const uint32_t*)(t0p + fc);
        a[1] = *(const uint32_t*)(t1p + fc);
        a[2] = *(const uint32_t*)(t0p + fc + 8);
        a[3] = *(const uint32_t*)(t1p + fc + 8);
        const float* un0 = &Un[(kk + fc) * SCS];
        const float* un1 = &Un[(kk + fc + 1) * SCS];
        const float* un8 = &Un[(kk + fc + 8) * SCS];
        const float* un9 = &Un[(kk + fc + 9) * SCS];
        int n = cnb + fr;
        uint32_t b0 = h2(un0[n], un1[n]);
        uint32_t b1 = h2(un8[n], un9[n]);
        mma16816(cacc, a, b0, b1);
      }
      int r0 = ctb + fr, r1 = ctb + fr + 8;
      float2 p0 = *(const float2*)&P[r0 * SCS + cnb + fc];
      float2 p1 = *(const float2*)&P[r1 * SCS + cnb + fc];
      size_t o0 = (((size_t)b * LL + (size_t)c * BT + r0) * HH + h) * DH + vb * 32 + cnb + fc;
      size_t o1 = (((size_t)b * LL + (size_t)c * BT + r1) * HH + h) * DH + vb * 32 + cnb + fc;
      *(float2*)&og[o0] = make_float2(p0.x + cacc[0], p0.y + cacc[1]);
      *(float2*)&og[o1] = make_float2(p1.x + cacc[2], p1.y + cacc[3]);
    }

    // ---- Phase D ----
    {
      float sacc[4][4];
#pragma unroll
      for (int vt = 0; vt < 4; vt++)
#pragma unroll
        for (int e = 0; e < 4; e++) sacc[vt][e] = 0.f;
#pragma unroll
      for (int s = 0; s < 4; s++) {
        int kk = s * 16;
        const float* un0 = &Un[(kk + fc) * SCS];
        const float* un1 = &Un[(kk + fc + 1) * SCS];
        const float* un8 = &Un[(kk + fc + 8) * SCS];
        const float* un9 = &Un[(kk + fc + 9) * SCS];
#pragma unroll
        for (int vt = 0; vt < 4; vt++) {
          uint32_t b0 = h2(un0[vt * 8 + fr], un1[vt * 8 + fr]);
          uint32_t b1 = h2(un8[vt * 8 + fr], un9[vt * 8 + fr]);
          mma16816(sacc[vt], ka[s], b0, b1);
        }
      }
#pragma unroll
      for (int vt = 0; vt < 4; vt++) {
        float2* sp0 = (float2*)&S[(dw + fr) * SCS + vt * 8 + fc];
        float2 v0r = *sp0;
        v0r.x += sacc[vt][0]; v0r.y += sacc[vt][1];
        *sp0 = v0r;
        float2* sp1 = (float2*)&S[(dw + fr + 8) * SCS + vt * 8 + fc];
        float2 v1r = *sp1;
        v1r.x += sacc[vt][2]; v1r.y += sacc[vt][3];
        *sp1 = v1r;
      }
    }
    CP_WAIT(0);
    __syncthreads();
  }
}

// -------------------- per-head RMSNorm * g_norm -> fp16 output --------------------
__global__ __launch_bounds__(256) void rms_kernel(
    const float* __restrict__ og, const float* __restrict__ gn, __half* __restrict__ on)
{
  int w = threadIdx.x >> 5, lane = threadIdx.x & 31;
  size_t idx = (size_t)blockIdx.x * 8 + w;
  const float* ip = og + idx * DH;
  float2 v[4];
  float ss = 0.f;
#pragma unroll
  for (int j = 0; j < 4; j++) {
    v[j] = *(const float2*)(ip + lane * 2 + j * 64);
    ss += v[j].x * v[j].x + v[j].y * v[j].y;
  }
#pragma unroll
  for (int o = 16; o; o >>= 1) ss += __shfl_xor_sync(0xffffffffu, ss, o);
  float scale = rsqrtf(ss * (1.f / DH) + 1e-5f);
  __half* op = on + idx * DH;
#pragma unroll
  for (int j = 0; j < 4; j++) {
    int e = lane * 2 + j * 64;
    float2 g = *(const float2*)(gn + e);
    __half2 hv = __floats2half2_rn(v[j].x * scale * g.x, v[j].y * scale * g.y);
    *(__half2*)(op + e) = hv;
  }
}

// -------------------- host launch --------------------
extern "C" void kernel_launch(void* const* d_in, const int* in_sizes, int n_in,
                              void* d_out, int out_size)
{
  const float* hs = (const float*)d_in[0];
  const float* Wq = (const float*)d_in[1];
  const float* Wk = (const float*)d_in[2];
  const float* Wv = (const float*)d_in[3];
  const float* Wb = (const float*)d_in[4];
  const float* cq = (const float*)d_in[5];
  const float* ck = (const float*)d_in[6];
  const float* cv = (const float*)d_in[7];
  const float* gn = (const float*)d_in[8];
  const float* Wo = (const float*)d_in[9];
  float* out = (float*)d_out;

  float *qt, *kt, *vt, *ut, *beta, *og;
  __half *preh, *qh, *khT, *ws, *atth, *ah, *wh;
  cudaGetSymbolAddress((void**)&preh, g_preh);
  cudaGetSymbolAddress((void**)&qt, g_qt);
  cudaGetSymbolAddress((void**)&kt, g_kt);
  cudaGetSymbolAddress((void**)&vt, g_vt);
  cudaGetSymbolAddress((void**)&ut, g_ut);
  cudaGetSymbolAddress((void**)&beta, g_beta);
  cudaGetSymbolAddress((void**)&og, g_og);
  cudaGetSymbolAddress((void**)&qh, g_qh);
  cudaGetSymbolAddress((void**)&khT, g_khT);
  cudaGetSymbolAddress((void**)&ws, g_ws);
  cudaGetSymbolAddress((void**)&atth, g_atth);
  cudaGetSymbolAddress((void**)&ah, g_ah);
  cudaGetSymbolAddress((void**)&wh, g_wh);

  cudaFuncSetAttribute(gemm_h_kernel, cudaFuncAttributeMaxDynamicSharedMemorySize, GEMM_SMEM);
  cudaFuncSetAttribute(solve_kernel, cudaFuncAttributeMaxDynamicSharedMemorySize, SOLVE_SMEM);
  cudaFuncSetAttribute(scan_kernel, cudaFuncAttributeMaxDynamicSharedMemorySize, SCAN_SMEM);

  const int actN4 = BLD / 4;

  // all QKV(+O) weights converted BEFORE the fused GEMM
  cvt_kernel<<<(actN4 + 255) / 256, 256>>>(hs, ah, actN4);
  cvt4_kernel<<<4 * 4096, 256>>>(Wq, Wk, Wv, Wo, wh);
  // fused QKV GEMM: C_half[M][6144]
  {
    dim3 gqkv(D3 / 128, (BB * LL) / 128);   // (48, 64)
    gemm_h_kernel<<<gqkv, 256, GEMM_SMEM>>>(ah, wh, (float*)0, preh,
                                            BB * LL, D3, DDIM, 1);
  }
  beta_kernel<<<BB * LL, 256>>>(hs, Wb, beta);

  conv_kernel<<<3 * BB * HH * (LL / 8), 256>>>(preh, cq, ck, cv, qt, kt, vt, qh, khT);

  solve_kernel<<<BB * HH * NC, 512, SOLVE_SMEM>>>(kt, vt, qt, beta, ws, ut, atth);
  scan_kernel<<<BB * HH * 8, 512, SCAN_SMEM>>>(qh, khT, ws, ut, atth, og);

  rms_kernel<<<BB * LL * HH / 8, 256>>>(og, gn, ah);
  {
    dim3 go(DDIM / 128, (BB * LL) / 128);
    gemm_h_kernel<<<go, 256, GEMM_SMEM>>>(ah, wh + 3 * (size_t)DD2, out, (__half*)0,
                                          BB * LL, DDIM, DDIM, 0);
  }
}